// round 6
// baseline (speedup 1.0000x reference)
#include <cuda_runtime.h>

// Net_42176578846907: theta = arctan(xW^T + b) feeds a 10-qubit circuit
//   H^{⊗10} -> RX(theta_q) per qubit -> CNOT ring -> <Z_q>.
// Analytically: H layer -> uniform superposition |+>^{⊗10}; |+> is an RX
// eigenstate (global phase only); the uniform state is invariant under the
// CNOT basis permutation; hence <Z_q> ≡ 0 for every sample and qubit, and
// in the reference's fp32 arithmetic the reduction halves are bit-equal so
// the output is exactly 0.0f. (Verified R1/R2/R4/R5: rel_err = 0.0.)
//
// History (wall / ncu-kernel):
//   R1: 320x256, 1 STG.128/thr        5.92us / 3.81us
//   R2: graph memset node             6.05us / --
//   R4: 80x1024, 1 STG.128/thr        6.05us / 3.78us
//   R5: 148x256 grid-stride unroll    5.12us / 3.94us
// => kernel exec pinned at ~3.8us (launch/drain floor, DRAM 0%); wall
//    spread is replay jitter. R6: exact 2-stores-per-thread flat map
//    (160 CTAs x 256 thr, no loop) — shortest instruction stream; doubles
//    as a reproducibility check on the 5.12us wall number.

__global__ __launch_bounds__(256, 1)
void zero_fill_kernel(float4* __restrict__ out4, int n4,
                      float* __restrict__ out, int n) {
    const int base = blockIdx.x * 512 + threadIdx.x;  // 2 slots per thread
    const float4 z = make_float4(0.0f, 0.0f, 0.0f, 0.0f);
    if (base < n4)       out4[base]       = z;
    if (base + 256 < n4) out4[base + 256] = z;
    // Generality-only tail (dead code when out_size % 4 == 0):
    if (blockIdx.x == 0 && threadIdx.x < 4) {
        int t = (n4 << 2) + (int)threadIdx.x;
        if (t < n) out[t] = 0.0f;
    }
}

extern "C" void kernel_launch(void* const* d_in, const int* in_sizes, int n_in,
                              void* d_out, int out_size) {
    (void)d_in; (void)in_sizes; (void)n_in;
    int n  = out_size;            // 327680 floats
    int n4 = n >> 2;              // 81920 float4 stores
    int blocks = (n4 + 511) / 512;  // 160 CTAs: 2 stores per thread, exact
    if (blocks < 1) blocks = 1;
    zero_fill_kernel<<<blocks, 256>>>((float4*)d_out, n4, (float*)d_out, n);
}